// round 6
// baseline (speedup 1.0000x reference)
#include <cuda_runtime.h>
#include <cstdint>

#define VOCAB 50257
#define EMBED 256
#define HID   128
#define G4    512   // 4*HID
#define BATCH 128
#define SEQ   1024

#define LOG2E 1.4426950408889634f

// Gate-projection table: table[v][g] = sum_e emb[v][e]*W_ih[g][e] + b_ih[g]+b_hh[g]
__device__ float g_table[(size_t)VOCAB * G4];

typedef unsigned long long ull;

// ---------------- packed fp32x2 helpers ----------------
__device__ __forceinline__ ull pack2(float lo, float hi) {
    ull r; asm("mov.b64 %0, {%1, %2};" : "=l"(r) : "f"(lo), "f"(hi)); return r;
}
__device__ __forceinline__ ull splat2(float x) {
    ull r; asm("mov.b64 %0, {%1, %1};" : "=l"(r) : "f"(x)); return r;
}
__device__ __forceinline__ void unpack2(ull v, float& lo, float& hi) {
    asm("mov.b64 {%0, %1}, %2;" : "=f"(lo), "=f"(hi) : "l"(v));
}
__device__ __forceinline__ void ffma2(ull& d, ull a, ull b) {
    asm("fma.rn.f32x2 %0, %1, %2, %0;" : "+l"(d) : "l"(a), "l"(b));
}
__device__ __forceinline__ float ex2f(float x) {
    float y; asm("ex2.approx.f32 %0, %1;" : "=f"(y) : "f"(x)); return y;
}
__device__ __forceinline__ float rcpf(float x) {
    float y; asm("rcp.approx.f32 %0, %1;" : "=f"(y) : "f"(x)); return y;
}
// packed bf16x2 (lo=even weight, hi=odd weight) -> f32x2 pair
__device__ __forceinline__ ull bf2pair(unsigned w) {
    unsigned lo = w << 16;
    unsigned hi = w & 0xffff0000u;
    ull r; asm("mov.b64 %0, {%1, %2};" : "=l"(r) : "r"(lo), "r"(hi));
    return r;
}
// pack two f32 into bf16x2 with round-to-nearest: result = [bf16(whi) : bf16(wlo)]
__device__ __forceinline__ unsigned bfpack(float wlo, float whi) {
    unsigned r;
    asm("cvt.rn.bf16x2.f32 %0, %1, %2;" : "=r"(r) : "f"(whi), "f"(wlo));
    return r;
}

// =====================================================================
// Kernel 1: table[v][g] = emb[v] . W_ih[g] + bias[g]
// 128x128 tile, 256 threads, 8x8 microtile, FFMA2, pre-packed SMEM,
// ping-pong SMEM buffers (ONE barrier per k-iter) + GMEM reg prefetch.
// =====================================================================
#define TBM 128
#define TBN 128
#define TKC 16
#define ASTRIDE (TBM + 2)   // ull stride
#define BSTRIDE (TBN + 4)   // float stride
#define NK_ITERS (EMBED / TKC)   // 16

__global__ void __launch_bounds__(256, 2) table_kernel(
    const float* __restrict__ emb,
    const float* __restrict__ W_ih,
    const float* __restrict__ b_ih,
    const float* __restrict__ b_hh)
{
    __shared__ ull   As2[2][TKC][ASTRIDE];  // splatted emb (ping-pong)
    __shared__ float Bs[2][TKC][BSTRIDE];   // W_ih transposed (ping-pong)

    const int v0 = blockIdx.x * TBM;
    const int g0 = blockIdx.y * TBN;
    const int tid = threadIdx.x;
    const int ty = tid >> 4;     // 0..15  (vocab octet)
    const int tx = tid & 15;     // 0..15  (gate octet)

    const int arow = tid >> 1;          // 0..127
    const int acol = (tid & 1) * 8;     // 0 or 8 (k offset)

    ull acc[8][4];
#pragma unroll
    for (int i = 0; i < 8; i++)
#pragma unroll
        for (int p = 0; p < 4; p++) acc[i][p] = 0ull;

    const int vload = min(v0 + arow, VOCAB - 1);
    const int grow  = g0 + arow;
    const float* aptr = emb  + (size_t)vload * EMBED + acol;
    const float* bptr = W_ih + (size_t)grow  * EMBED + acol;

    // prefetch iteration 0
    float4 ra0 = *(const float4*)(aptr);
    float4 ra1 = *(const float4*)(aptr + 4);
    float4 rb0 = *(const float4*)(bptr);
    float4 rb1 = *(const float4*)(bptr + 4);

    for (int it = 0; it < NK_ITERS; it++) {
        const int pb = it & 1;
        // store current tile into SMEM buffer pb
        As2[pb][acol + 0][arow] = splat2(ra0.x); As2[pb][acol + 1][arow] = splat2(ra0.y);
        As2[pb][acol + 2][arow] = splat2(ra0.z); As2[pb][acol + 3][arow] = splat2(ra0.w);
        As2[pb][acol + 4][arow] = splat2(ra1.x); As2[pb][acol + 5][arow] = splat2(ra1.y);
        As2[pb][acol + 6][arow] = splat2(ra1.z); As2[pb][acol + 7][arow] = splat2(ra1.w);
        Bs[pb][acol + 0][arow] = rb0.x; Bs[pb][acol + 1][arow] = rb0.y;
        Bs[pb][acol + 2][arow] = rb0.z; Bs[pb][acol + 3][arow] = rb0.w;
        Bs[pb][acol + 4][arow] = rb1.x; Bs[pb][acol + 5][arow] = rb1.y;
        Bs[pb][acol + 6][arow] = rb1.z; Bs[pb][acol + 7][arow] = rb1.w;
        __syncthreads();

        // issue next tile's GMEM loads (latency hidden under compute)
        {
            int knext = min((it + 1) * TKC, EMBED - TKC);
            ra0 = *(const float4*)(aptr + knext);
            ra1 = *(const float4*)(aptr + knext + 4);
            rb0 = *(const float4*)(bptr + knext);
            rb1 = *(const float4*)(bptr + knext + 4);
        }

#pragma unroll
        for (int k = 0; k < TKC; k++) {
            ulonglong2 bp0 = *(const ulonglong2*)&Bs[pb][k][tx * 8];
            ulonglong2 bp1 = *(const ulonglong2*)&Bs[pb][k][tx * 8 + 4];
            ull b2[4] = { bp0.x, bp0.y, bp1.x, bp1.y };
            const ulonglong2* ap = (const ulonglong2*)&As2[pb][k][ty * 8];
            ulonglong2 a01 = ap[0], a23 = ap[1], a45 = ap[2], a67 = ap[3];
            ull av[8] = { a01.x, a01.y, a23.x, a23.y, a45.x, a45.y, a67.x, a67.y };
#pragma unroll
            for (int i = 0; i < 8; i++)
#pragma unroll
                for (int p = 0; p < 4; p++)
                    ffma2(acc[i][p], av[i], b2[p]);
        }
        // no trailing barrier: ping-pong buffers; the next iteration's barrier
        // protects buffer reuse.
    }

    // epilogue: add bias, store
    const int gbase = g0 + tx * 8;
    float bz[8];
#pragma unroll
    for (int c = 0; c < 8; c++) bz[c] = b_ih[gbase + c] + b_hh[gbase + c];

#pragma unroll
    for (int i = 0; i < 8; i++) {
        int v = v0 + ty * 8 + i;
        if (v < VOCAB) {
            float r[8];
#pragma unroll
            for (int p = 0; p < 4; p++) {
                float lo, hi;
                unpack2(acc[i][p], lo, hi);
                r[2 * p]     = lo + bz[2 * p];
                r[2 * p + 1] = hi + bz[2 * p + 1];
            }
            float* dst = &g_table[(size_t)v * G4 + gbase];
            *(float4*)(dst)     = make_float4(r[0], r[1], r[2], r[3]);
            *(float4*)(dst + 4) = make_float4(r[4], r[5], r[6], r[7]);
        }
    }
}

// =====================================================================
// Kernel 2: per-batch LSTM recurrence. 128 CTAs x 512 threads.
// Thread = (unit j = tid>>2, k-quarter q = tid&3).
// acc_m at lane q accumulates gate (q^m) over k in [32q,32q+32).
// Gates q^0..q^2 fp32 in regs (96 regs); gate q^3 bf16x2 in SMEM
// (4 LDS.128/step, minimum crossbar bytes). No prefetch ring, no
// unroll-2, slim working set -> no register spills at 512 thr/CTA.
// h skewed + double-buffered. One barrier per step.
// =====================================================================
#define HSKB 148   // floats per h buffer (4 slices of 36 + pad)

struct __align__(16) LstmSmem {
    uint4 wsb[4][512];        // bf16x2-packed SMEM-gate weights, 32 KB
    float hsk[2][HSKB];       // double-buffered skewed h
    float hred[256];          // head scratch
    int   toff[SEQ + 2];      // token BYTE offsets into g_table (padded)
};

__global__ void __launch_bounds__(512, 1) lstm_kernel(
    const void* __restrict__ xraw,
    const float* __restrict__ W_hh,
    const float* __restrict__ W_fc,
    const float* __restrict__ b_fc,
    float* __restrict__ out)
{
    extern __shared__ char smem_raw[];
    LstmSmem* S = (LstmSmem*)smem_raw;

    const int b = blockIdx.x;
    const int tid = threadIdx.x;
    const int j = tid >> 2;   // hidden unit 0..127
    const int q = tid & 3;    // k-quarter 0..3

    // --- detect whether x is stored as int64 or int32 ---
    bool is64;
    {
        const int* xi = (const int*)xraw;
        int val = xi[2 * (tid & 31) + 1];
        unsigned m = __ballot_sync(0xffffffffu, val != 0);
        is64 = (m == 0u);
    }

    // --- preload token byte-offsets (tok * 2048 bytes), pad last ---
    if (is64) {
        const long long* x64 = (const long long*)xraw + (size_t)b * SEQ;
        for (int i = tid; i <= SEQ; i += 512) {
            int src = min(i, SEQ - 1);
            S->toff[i] = ((int)x64[src]) << 11;
        }
    } else {
        const int* x32 = (const int*)xraw + (size_t)b * SEQ;
        for (int i = tid; i <= SEQ; i += 512) {
            int src = min(i, SEQ - 1);
            S->toff[i] = x32[src] << 11;
        }
    }

    // --- weights. acc_m holds gate (q^m); m=0..2 -> fp32 regs, m=3 -> bf16 SMEM ---
    ull wreg[48];
#pragma unroll
    for (int m = 0; m < 3; m++) {
        const float4* src = (const float4*)(W_hh + (size_t)((q ^ m) * HID + j) * HID + q * 32);
#pragma unroll
        for (int u = 0; u < 8; u++) {
            float4 w = src[u];
            wreg[m * 16 + 2 * u]     = pack2(w.x, w.y);
            wreg[m * 16 + 2 * u + 1] = pack2(w.z, w.w);
        }
    }
    {
        const float4* src = (const float4*)(W_hh + (size_t)((q ^ 3) * HID + j) * HID + q * 32);
#pragma unroll
        for (int u = 0; u < 4; u++) {
            float4 w0 = src[2 * u];
            float4 w1 = src[2 * u + 1];
            uint4 pk;
            pk.x = bfpack(w0.x, w0.y);
            pk.y = bfpack(w0.z, w0.w);
            pk.z = bfpack(w1.x, w1.y);
            pk.w = bfpack(w1.z, w1.w);
            S->wsb[u][tid] = pk;
        }
    }

    // zero both h buffers
    for (int i = tid; i < 2 * HSKB; i += 512) ((float*)S->hsk)[i] = 0.0f;

    float c = 0.0f;
    // lane q's z is gate q: 0=i,1=f,3=o sigmoid; 2=g tanh (as 2*sig(2z)-1)
    const float am = (q == 2) ? 2.0f : 1.0f;
    const float ab = (q == 2) ? -1.0f : 0.0f;
    const float ae = -LOG2E * am;
    const bool hwriter = (q == (j >> 5));
    const int hwidx = q * 36 + (j & 31);
    __syncthreads();

    const char* tabq = (const char*)g_table + (size_t)(q * HID + j) * 4;
    float xgq = *(const float*)(tabq + S->toff[0]);

    const ulonglong2* hp0 = (const ulonglong2*)(S->hsk[0] + q * 36);
    const ulonglong2* hp1 = (const ulonglong2*)(S->hsk[1] + q * 36);
    const uint4* wsp = &S->wsb[0][tid];   // row stride = 512 uint4

    for (int t = 0; t < SEQ; t++) {
        const ulonglong2* hp = (t & 1) ? hp1 : hp0;

        // prefetch next step's table entry (independent of h)
        float xg_nxt = *(const float*)(tabq + S->toff[t + 1]);

        // ---- 4 gate-partial chains; xgq folded into acc0's init ----
        ull acc0 = pack2(xgq, 0.0f);
        ull acc1 = 0ull, acc2 = 0ull, acc3 = 0ull;
#pragma unroll
        for (int u = 0; u < 4; u++) {
            uint4 wv = wsp[u * 512];          // bf16 o-gate weights, loaded in-loop
            ulonglong2 hv0 = hp[2 * u];
            ulonglong2 hv1 = hp[2 * u + 1];
            ffma2(acc0, wreg[4 * u],          hv0.x);
            ffma2(acc1, wreg[16 + 4 * u],     hv0.x);
            ffma2(acc2, wreg[32 + 4 * u],     hv0.x);
            ffma2(acc0, wreg[4 * u + 1],      hv0.y);
            ffma2(acc1, wreg[16 + 4 * u + 1], hv0.y);
            ffma2(acc2, wreg[32 + 4 * u + 1], hv0.y);
            ffma2(acc0, wreg[4 * u + 2],      hv1.x);
            ffma2(acc1, wreg[16 + 4 * u + 2], hv1.x);
            ffma2(acc2, wreg[32 + 4 * u + 2], hv1.x);
            ffma2(acc0, wreg[4 * u + 3],      hv1.y);
            ffma2(acc1, wreg[16 + 4 * u + 3], hv1.y);
            ffma2(acc2, wreg[32 + 4 * u + 3], hv1.y);
            ffma2(acc3, bf2pair(wv.x),        hv0.x);
            ffma2(acc3, bf2pair(wv.y),        hv0.y);
            ffma2(acc3, bf2pair(wv.z),        hv1.x);
            ffma2(acc3, bf2pair(wv.w),        hv1.y);
        }

        float p0, p1, p2, p3, lo, hi;
        unpack2(acc0, lo, hi); p0 = lo + hi;
        unpack2(acc1, lo, hi); p1 = lo + hi;
        unpack2(acc2, lo, hi); p2 = lo + hi;
        unpack2(acc3, lo, hi); p3 = lo + hi;

        // ---- reduce: lane q ends with full z of gate q ----
        float s0 = p0 + __shfl_xor_sync(0xffffffffu, p1, 1);
        float s1 = p2 + __shfl_xor_sync(0xffffffffu, p3, 1);
        float z  = s0 + __shfl_xor_sync(0xffffffffu, s1, 2);

        // ---- activation for gate q (uniform sigmoid path) ----
        float e = ex2f(ae * z);
        float s = rcpf(1.0f + e);
        float a = fmaf(am, s, ab);

        // ---- gather the four activations by absolute lane (width=4) ----
        float gi_ = __shfl_sync(0xffffffffu, a, 0, 4);
        float gf_ = __shfl_sync(0xffffffffu, a, 1, 4);
        float gg_ = __shfl_sync(0xffffffffu, a, 2, 4);
        float go_ = __shfl_sync(0xffffffffu, a, 3, 4);

        // ---- cell/hidden update (identical across the 4 lanes of unit j) ----
        c = fmaf(gf_, c, gi_ * gg_);
        float tc = fmaf(2.0f, rcpf(1.0f + ex2f(-2.0f * LOG2E * c)), -1.0f);
        float h = go_ * tc;
        if (hwriter) S->hsk[(t + 1) & 1][hwidx] = h;

        xgq = xg_nxt;
        __syncthreads();
    }

    // --- final linear head (h(SEQ) lives in buffer 0 since SEQ is even) ---
    if (tid < 256) {
        int cls = tid >> 7;
        int jj  = tid & 127;
        float hv = S->hsk[0][(jj >> 5) * 36 + (jj & 31)];
        S->hred[tid] = hv * W_fc[cls * HID + jj];
    }
    __syncthreads();
    if (tid < 2) {
        float s = b_fc[tid];
#pragma unroll 8
        for (int jj = 0; jj < HID; jj++) s += S->hred[tid * HID + jj];
        out[b * 2 + tid] = s;
    }
}

// =====================================================================
extern "C" void kernel_launch(void* const* d_in, const int* in_sizes, int n_in,
                              void* d_out, int out_size)
{
    const void*  x     = d_in[0];
    const float* emb   = (const float*)d_in[1];
    const float* W_ih  = (const float*)d_in[2];
    const float* W_hh  = (const float*)d_in[3];
    const float* b_ih  = (const float*)d_in[4];
    const float* b_hh  = (const float*)d_in[5];
    const float* W_fc  = (const float*)d_in[6];
    const float* b_fc  = (const float*)d_in[7];
    float* out = (float*)d_out;

    dim3 tgrid((VOCAB + TBM - 1) / TBM, G4 / TBN);   // 393 x 4
    table_kernel<<<tgrid, 256>>>(emb, W_ih, b_ih, b_hh);

    const int smem_bytes = (int)sizeof(LstmSmem);
    cudaFuncSetAttribute(lstm_kernel, cudaFuncAttributeMaxDynamicSharedMemorySize, smem_bytes);
    lstm_kernel<<<BATCH, 512, smem_bytes>>>(x, W_hh, W_fc, b_fc, out);
}

// round 7
// speedup vs baseline: 1.0678x; 1.0678x over previous
#include <cuda_runtime.h>
#include <cstdint>

#define VOCAB 50257
#define EMBED 256
#define HID   128
#define G4    512   // 4*HID
#define BATCH 128
#define SEQ   1024

#define LOG2E 1.4426950408889634f

// Gate-projection table: table[v][g] = sum_e emb[v][e]*W_ih[g][e] + b_ih[g]+b_hh[g]
__device__ float g_table[(size_t)VOCAB * G4];

typedef unsigned long long ull;

// ---------------- packed fp32x2 helpers ----------------
__device__ __forceinline__ ull pack2(float lo, float hi) {
    ull r; asm("mov.b64 %0, {%1, %2};" : "=l"(r) : "f"(lo), "f"(hi)); return r;
}
__device__ __forceinline__ ull splat2(float x) {
    ull r; asm("mov.b64 %0, {%1, %1};" : "=l"(r) : "f"(x)); return r;
}
__device__ __forceinline__ void unpack2(ull v, float& lo, float& hi) {
    asm("mov.b64 {%0, %1}, %2;" : "=f"(lo), "=f"(hi) : "l"(v));
}
__device__ __forceinline__ void ffma2(ull& d, ull a, ull b) {
    asm("fma.rn.f32x2 %0, %1, %2, %0;" : "+l"(d) : "l"(a), "l"(b));
}
__device__ __forceinline__ float ex2f(float x) {
    float y; asm("ex2.approx.f32 %0, %1;" : "=f"(y) : "f"(x)); return y;
}
__device__ __forceinline__ float rcpf(float x) {
    float y; asm("rcp.approx.f32 %0, %1;" : "=f"(y) : "f"(x)); return y;
}
__device__ __forceinline__ float tanhaf(float x) {
    float y; asm("tanh.approx.f32 %0, %1;" : "=f"(y) : "f"(x)); return y;
}
// packed bf16x2 (lo=even weight, hi=odd weight) -> f32x2 pair
__device__ __forceinline__ ull bf2pair(unsigned w) {
    unsigned lo = w << 16;
    unsigned hi = w & 0xffff0000u;
    ull r; asm("mov.b64 %0, {%1, %2};" : "=l"(r) : "r"(lo), "r"(hi));
    return r;
}
// pack two f32 into bf16x2 with round-to-nearest: [bf16(whi) : bf16(wlo)]
__device__ __forceinline__ unsigned bfpack(float wlo, float whi) {
    unsigned r;
    asm("cvt.rn.bf16x2.f32 %0, %1, %2;" : "=r"(r) : "f"(whi), "f"(wlo));
    return r;
}

// =====================================================================
// Kernel 1: table[v][g] = emb[v] . W_ih[g] + bias[g]
// 128x128 tile, 256 threads, 8x8 microtile, FFMA2, pre-packed SMEM,
// ping-pong SMEM buffers (ONE barrier per k-iter) + GMEM reg prefetch.
// =====================================================================
#define TBM 128
#define TBN 128
#define TKC 16
#define ASTRIDE (TBM + 2)
#define BSTRIDE (TBN + 4)
#define NK_ITERS (EMBED / TKC)   // 16

__global__ void __launch_bounds__(256, 2) table_kernel(
    const float* __restrict__ emb,
    const float* __restrict__ W_ih,
    const float* __restrict__ b_ih,
    const float* __restrict__ b_hh)
{
    __shared__ ull   As2[2][TKC][ASTRIDE];
    __shared__ float Bs[2][TKC][BSTRIDE];

    const int v0 = blockIdx.x * TBM;
    const int g0 = blockIdx.y * TBN;
    const int tid = threadIdx.x;
    const int ty = tid >> 4;
    const int tx = tid & 15;

    const int arow = tid >> 1;
    const int acol = (tid & 1) * 8;

    ull acc[8][4];
#pragma unroll
    for (int i = 0; i < 8; i++)
#pragma unroll
        for (int p = 0; p < 4; p++) acc[i][p] = 0ull;

    const int vload = min(v0 + arow, VOCAB - 1);
    const int grow  = g0 + arow;
    const float* aptr = emb  + (size_t)vload * EMBED + acol;
    const float* bptr = W_ih + (size_t)grow  * EMBED + acol;

    float4 ra0 = *(const float4*)(aptr);
    float4 ra1 = *(const float4*)(aptr + 4);
    float4 rb0 = *(const float4*)(bptr);
    float4 rb1 = *(const float4*)(bptr + 4);

    for (int it = 0; it < NK_ITERS; it++) {
        const int pb = it & 1;
        As2[pb][acol + 0][arow] = splat2(ra0.x); As2[pb][acol + 1][arow] = splat2(ra0.y);
        As2[pb][acol + 2][arow] = splat2(ra0.z); As2[pb][acol + 3][arow] = splat2(ra0.w);
        As2[pb][acol + 4][arow] = splat2(ra1.x); As2[pb][acol + 5][arow] = splat2(ra1.y);
        As2[pb][acol + 6][arow] = splat2(ra1.z); As2[pb][acol + 7][arow] = splat2(ra1.w);
        Bs[pb][acol + 0][arow] = rb0.x; Bs[pb][acol + 1][arow] = rb0.y;
        Bs[pb][acol + 2][arow] = rb0.z; Bs[pb][acol + 3][arow] = rb0.w;
        Bs[pb][acol + 4][arow] = rb1.x; Bs[pb][acol + 5][arow] = rb1.y;
        Bs[pb][acol + 6][arow] = rb1.z; Bs[pb][acol + 7][arow] = rb1.w;
        __syncthreads();

        {
            int knext = min((it + 1) * TKC, EMBED - TKC);
            ra0 = *(const float4*)(aptr + knext);
            ra1 = *(const float4*)(aptr + knext + 4);
            rb0 = *(const float4*)(bptr + knext);
            rb1 = *(const float4*)(bptr + knext + 4);
        }

#pragma unroll
        for (int k = 0; k < TKC; k++) {
            ulonglong2 bp0 = *(const ulonglong2*)&Bs[pb][k][tx * 8];
            ulonglong2 bp1 = *(const ulonglong2*)&Bs[pb][k][tx * 8 + 4];
            ull b2[4] = { bp0.x, bp0.y, bp1.x, bp1.y };
            const ulonglong2* ap = (const ulonglong2*)&As2[pb][k][ty * 8];
            ulonglong2 a01 = ap[0], a23 = ap[1], a45 = ap[2], a67 = ap[3];
            ull av[8] = { a01.x, a01.y, a23.x, a23.y, a45.x, a45.y, a67.x, a67.y };
#pragma unroll
            for (int i = 0; i < 8; i++)
#pragma unroll
                for (int p = 0; p < 4; p++)
                    ffma2(acc[i][p], av[i], b2[p]);
        }
    }

    const int gbase = g0 + tx * 8;
    float bz[8];
#pragma unroll
    for (int c = 0; c < 8; c++) bz[c] = b_ih[gbase + c] + b_hh[gbase + c];

#pragma unroll
    for (int i = 0; i < 8; i++) {
        int v = v0 + ty * 8 + i;
        if (v < VOCAB) {
            float r[8];
#pragma unroll
            for (int p = 0; p < 4; p++) {
                float lo, hi;
                unpack2(acc[i][p], lo, hi);
                r[2 * p]     = lo + bz[2 * p];
                r[2 * p + 1] = hi + bz[2 * p + 1];
            }
            float* dst = &g_table[(size_t)v * G4 + gbase];
            *(float4*)(dst)     = make_float4(r[0], r[1], r[2], r[3]);
            *(float4*)(dst + 4) = make_float4(r[4], r[5], r[6], r[7]);
        }
    }
}

// =====================================================================
// Kernel 2: per-batch LSTM recurrence. 128 CTAs x 512 threads.
// Thread = (unit j = tid>>2, k-quarter q = tid&3).
// acc_m at lane q accumulates gate (q^m) over k in [32q,32q+32).
// REG BUDGET: 40 f32x2 weight pairs in regs (80 regs): m=0,1 full
// (16 pairs each) + m=2 lower 8 pairs. SMEM bf16x2: m=3 full (rows 0-3)
// + m=2 upper 8 pairs (rows 4-5). Target < 128 regs -> NO SPILLS.
// tanh.approx for tanh(c) (output path only). One barrier per step.
// =====================================================================
#define HSKB 148   // floats per h buffer (4 slices of 36 + pad)

struct __align__(16) LstmSmem {
    uint4 wsb[6][512];        // bf16x2-packed SMEM weights, 48 KB
    float hsk[2][HSKB];       // double-buffered skewed h
    float hred[256];          // head scratch
    int   toff[SEQ + 2];      // token BYTE offsets into g_table (padded)
};

__global__ void __launch_bounds__(512, 1) lstm_kernel(
    const void* __restrict__ xraw,
    const float* __restrict__ W_hh,
    const float* __restrict__ W_fc,
    const float* __restrict__ b_fc,
    float* __restrict__ out)
{
    extern __shared__ char smem_raw[];
    LstmSmem* S = (LstmSmem*)smem_raw;

    const int b = blockIdx.x;
    const int tid = threadIdx.x;
    const int j = tid >> 2;   // hidden unit 0..127
    const int q = tid & 3;    // k-quarter 0..3

    // --- detect whether x is stored as int64 or int32 ---
    bool is64;
    {
        const int* xi = (const int*)xraw;
        int val = xi[2 * (tid & 31) + 1];
        unsigned m = __ballot_sync(0xffffffffu, val != 0);
        is64 = (m == 0u);
    }

    // --- preload token byte-offsets (tok * 2048 bytes), pad last ---
    if (is64) {
        const long long* x64 = (const long long*)xraw + (size_t)b * SEQ;
        for (int i = tid; i <= SEQ; i += 512) {
            int src = min(i, SEQ - 1);
            S->toff[i] = ((int)x64[src]) << 11;
        }
    } else {
        const int* x32 = (const int*)xraw + (size_t)b * SEQ;
        for (int i = tid; i <= SEQ; i += 512) {
            int src = min(i, SEQ - 1);
            S->toff[i] = x32[src] << 11;
        }
    }

    // --- weights. acc_m holds gate (q^m). ---
    // regs: m=0 -> wreg[0..15], m=1 -> wreg[16..31], m=2 lower -> wreg[32..39]
    ull wreg[40];
#pragma unroll
    for (int m = 0; m < 2; m++) {
        const float4* src = (const float4*)(W_hh + (size_t)((q ^ m) * HID + j) * HID + q * 32);
#pragma unroll
        for (int u = 0; u < 8; u++) {
            float4 w = src[u];
            wreg[m * 16 + 2 * u]     = pack2(w.x, w.y);
            wreg[m * 16 + 2 * u + 1] = pack2(w.z, w.w);
        }
    }
    {   // m=2: lower 8 pairs (k 0..15 of slice) to regs, upper 8 pairs to bf16 SMEM rows 4,5
        const float4* src = (const float4*)(W_hh + (size_t)((q ^ 2) * HID + j) * HID + q * 32);
#pragma unroll
        for (int u = 0; u < 4; u++) {
            float4 w = src[u];
            wreg[32 + 2 * u]     = pack2(w.x, w.y);
            wreg[32 + 2 * u + 1] = pack2(w.z, w.w);
        }
#pragma unroll
        for (int u2 = 0; u2 < 2; u2++) {
            float4 w0 = src[4 + 2 * u2];
            float4 w1 = src[5 + 2 * u2];
            uint4 pk;
            pk.x = bfpack(w0.x, w0.y);
            pk.y = bfpack(w0.z, w0.w);
            pk.z = bfpack(w1.x, w1.y);
            pk.w = bfpack(w1.z, w1.w);
            S->wsb[4 + u2][tid] = pk;
        }
    }
    {   // m=3: all 16 pairs bf16 SMEM rows 0..3
        const float4* src = (const float4*)(W_hh + (size_t)((q ^ 3) * HID + j) * HID + q * 32);
#pragma unroll
        for (int u = 0; u < 4; u++) {
            float4 w0 = src[2 * u];
            float4 w1 = src[2 * u + 1];
            uint4 pk;
            pk.x = bfpack(w0.x, w0.y);
            pk.y = bfpack(w0.z, w0.w);
            pk.z = bfpack(w1.x, w1.y);
            pk.w = bfpack(w1.z, w1.w);
            S->wsb[u][tid] = pk;
        }
    }

    // zero both h buffers
    for (int i = tid; i < 2 * HSKB; i += 512) ((float*)S->hsk)[i] = 0.0f;

    float c = 0.0f;
    // lane q's z is gate q: 0=i,1=f,3=o sigmoid; 2=g tanh (as 2*sig(2z)-1)
    const float am = (q == 2) ? 2.0f : 1.0f;   // ab = 1-am, exp scale derived in tail
    const bool hwriter = (q == (j >> 5));
    const int hwidx = q * 36 + (j & 31);
    __syncthreads();

    const char* tabq = (const char*)g_table + (size_t)(q * HID + j) * 4;
    float xgq = *(const float*)(tabq + S->toff[0]);

    const float* hbase = S->hsk[0] + q * 36;
    const uint4* wsp = &S->wsb[0][tid];   // row stride = 512 uint4

    for (int t = 0; t < SEQ; t++) {
        const ulonglong2* hp = (const ulonglong2*)(hbase + (t & 1) * HSKB);

        // prefetch next step's table entry (independent of h)
        float xg_nxt = *(const float*)(tabq + S->toff[t + 1]);

        // ---- 4 gate-partial chains; xgq folded into acc0's init ----
        ull acc0 = pack2(xgq, 0.0f);
        ull acc1 = 0ull, acc2 = 0ull, acc3 = 0ull;
#pragma unroll
        for (int u = 0; u < 4; u++) {
            uint4 wv = wsp[u * 512];          // m=3 bf16 weights
            ulonglong2 hv0 = hp[2 * u];
            ulonglong2 hv1 = hp[2 * u + 1];
            ffma2(acc0, wreg[4 * u],          hv0.x);
            ffma2(acc1, wreg[16 + 4 * u],     hv0.x);
            ffma2(acc0, wreg[4 * u + 1],      hv0.y);
            ffma2(acc1, wreg[16 + 4 * u + 1], hv0.y);
            ffma2(acc0, wreg[4 * u + 2],      hv1.x);
            ffma2(acc1, wreg[16 + 4 * u + 2], hv1.x);
            ffma2(acc0, wreg[4 * u + 3],      hv1.y);
            ffma2(acc1, wreg[16 + 4 * u + 3], hv1.y);
            if (u < 2) {
                // m=2 lower half from regs
                ffma2(acc2, wreg[32 + 4 * u],     hv0.x);
                ffma2(acc2, wreg[32 + 4 * u + 1], hv0.y);
                ffma2(acc2, wreg[32 + 4 * u + 2], hv1.x);
                ffma2(acc2, wreg[32 + 4 * u + 3], hv1.y);
            } else {
                // m=2 upper half from bf16 SMEM rows 4,5
                uint4 wv2 = wsp[(4 + (u - 2)) * 512];
                ffma2(acc2, bf2pair(wv2.x), hv0.x);
                ffma2(acc2, bf2pair(wv2.y), hv0.y);
                ffma2(acc2, bf2pair(wv2.z), hv1.x);
                ffma2(acc2, bf2pair(wv2.w), hv1.y);
            }
            ffma2(acc3, bf2pair(wv.x), hv0.x);
            ffma2(acc3, bf2pair(wv.y), hv0.y);
            ffma2(acc3, bf2pair(wv.z), hv1.x);
            ffma2(acc3, bf2pair(wv.w), hv1.y);
        }

        float p0, p1, p2, p3, lo, hi;
        unpack2(acc0, lo, hi); p0 = lo + hi;
        unpack2(acc1, lo, hi); p1 = lo + hi;
        unpack2(acc2, lo, hi); p2 = lo + hi;
        unpack2(acc3, lo, hi); p3 = lo + hi;

        // ---- reduce: lane q ends with full z of gate q ----
        float s0 = p0 + __shfl_xor_sync(0xffffffffu, p1, 1);
        float s1 = p2 + __shfl_xor_sync(0xffffffffu, p3, 1);
        float z  = s0 + __shfl_xor_sync(0xffffffffu, s1, 2);

        // ---- activation for gate q (uniform sigmoid path, consts from am) ----
        float e = ex2f((z * am) * (-LOG2E));
        float s = rcpf(1.0f + e);
        float a = fmaf(am, s, 1.0f - am);   // sigmoid (am=1) or tanh (am=2)

        // ---- gather the four activations by absolute lane (width=4) ----
        float gi_ = __shfl_sync(0xffffffffu, a, 0, 4);
        float gf_ = __shfl_sync(0xffffffffu, a, 1, 4);
        float gg_ = __shfl_sync(0xffffffffu, a, 2, 4);
        float go_ = __shfl_sync(0xffffffffu, a, 3, 4);

        // ---- cell/hidden update (identical across the 4 lanes of unit j) ----
        c = fmaf(gf_, c, gi_ * gg_);
        float h = go_ * tanhaf(c);          // output path only: approx OK
        if (hwriter) S->hsk[(t + 1) & 1][hwidx] = h;

        xgq = xg_nxt;
        __syncthreads();
    }

    // --- final linear head (h(SEQ) lives in buffer 0 since SEQ is even) ---
    if (tid < 256) {
        int cls = tid >> 7;
        int jj  = tid & 127;
        float hv = S->hsk[0][(jj >> 5) * 36 + (jj & 31)];
        S->hred[tid] = hv * W_fc[cls * HID + jj];
    }
    __syncthreads();
    if (tid < 2) {
        float s = b_fc[tid];
#pragma unroll 8
        for (int jj = 0; jj < HID; jj++) s += S->hred[tid * HID + jj];
        out[b * 2 + tid] = s;
    }
}

// =====================================================================
extern "C" void kernel_launch(void* const* d_in, const int* in_sizes, int n_in,
                              void* d_out, int out_size)
{
    const void*  x     = d_in[0];
    const float* emb   = (const float*)d_in[1];
    const float* W_ih  = (const float*)d_in[2];
    const float* W_hh  = (const float*)d_in[3];
    const float* b_ih  = (const float*)d_in[4];
    const float* b_hh  = (const float*)d_in[5];
    const float* W_fc  = (const float*)d_in[6];
    const float* b_fc  = (const float*)d_in[7];
    float* out = (float*)d_out;

    dim3 tgrid((VOCAB + TBM - 1) / TBM, G4 / TBN);   // 393 x 4
    table_kernel<<<tgrid, 256>>>(emb, W_ih, b_ih, b_hh);

    const int smem_bytes = (int)sizeof(LstmSmem);
    cudaFuncSetAttribute(lstm_kernel, cudaFuncAttributeMaxDynamicSharedMemorySize, smem_bytes);
    lstm_kernel<<<BATCH, 512, smem_bytes>>>(x, W_hh, W_fc, b_fc, out);
}